// round 15
// baseline (speedup 1.0000x reference)
#include <cuda_runtime.h>

#define EPS     1e-8f
#define PSD_EPS 1e-5f

constexpr int B = 8, C = 8, F = 257, T = 1500;
constexpr int BF  = B * F;                       // 2056
constexpr long long FT  = (long long)F * T;      // 385500
constexpr long long BFT = (long long)B * F * T;  // 3084000
constexpr int T4 = T / 4;                        // 375
constexpr int NCH = 32;                          // F-chunks for mask max
constexpr int NCHUNK = 5;                        // cp.async pipeline chunks
constexpr int CH_T = T / NCHUNK;                 // 300 t per chunk
constexpr int CH_T4 = CH_T / 4;                  // 75 float4 per row-chunk
constexpr int CH_T2 = CH_T / 2;                  // 150 float2 per chunk
constexpr int EPC = 16 * CH_T4;                  // 1200 float4 elements per chunk

// Scratch (no allocations allowed)
__device__ float g_pmax[2][B][NCH][T];
__device__ float g_recip[2][B][T];

// ---------------------------------------------------------------------------
// cp.async helpers
// ---------------------------------------------------------------------------
__device__ __forceinline__ unsigned smem_u32(const void* p) {
    return (unsigned)__cvta_generic_to_shared(p);
}
__device__ __forceinline__ void cp16(unsigned dst, const void* src) {
    asm volatile("cp.async.cg.shared.global [%0], [%1], 16;" :: "r"(dst), "l"(src));
}
__device__ __forceinline__ void cp_commit() {
    asm volatile("cp.async.commit_group;");
}
template <int N> __device__ __forceinline__ void cp_wait() {
    asm volatile("cp.async.wait_group %0;" :: "n"(N));
}

// ---------------------------------------------------------------------------
// Kernel 1a: partial max over F-chunk of |mask|, float4 along t.
// grid = 2*B*NCH = 512 blocks, 384 threads (375 active).
// ---------------------------------------------------------------------------
__global__ void mask_max_part(const float* __restrict__ sm,
                              const float* __restrict__ nm) {
    int blk = blockIdx.x;
    int chunk = blk & (NCH - 1), b = (blk >> 5) & 7, m = blk >> 8;
    int i = threadIdx.x;
    if (i >= T4) return;
    // F = 257 = 9 + 31*8
    int fs = chunk ? 9 + (chunk - 1) * 8 : 0;
    int fe = fs + (chunk ? 8 : 9);
    const float4* src = (const float4*)((m ? nm : sm) + (long long)b * FT);
    float4 mx = make_float4(0.f, 0.f, 0.f, 0.f);
    #pragma unroll 4
    for (int f = fs; f < fe; f++) {
        float4 v = src[(long long)f * T4 + i];
        mx.x = fmaxf(mx.x, fabsf(v.x));
        mx.y = fmaxf(mx.y, fabsf(v.y));
        mx.z = fmaxf(mx.z, fabsf(v.z));
        mx.w = fmaxf(mx.w, fabsf(v.w));
    }
    ((float4*)g_pmax[m][b][chunk])[i] = mx;
}

// Kernel 1b: combine NCH partials -> reciprocal. grid = 16 blocks.
__global__ void mask_recip_kernel() {
    int blk = blockIdx.x;
    int b = blk & 7, m = blk >> 3;
    int i = threadIdx.x;
    if (i >= T4) return;
    float4 a = ((float4*)g_pmax[m][b][0])[i];
    #pragma unroll
    for (int c = 1; c < NCH; c++) {
        float4 v = ((float4*)g_pmax[m][b][c])[i];
        a.x = fmaxf(a.x, v.x); a.y = fmaxf(a.y, v.y);
        a.z = fmaxf(a.z, v.z); a.w = fmaxf(a.w, v.w);
    }
    float4 r;
    r.x = 1.0f / (a.x + EPS); r.y = 1.0f / (a.y + EPS);
    r.z = 1.0f / (a.z + EPS); r.w = 1.0f / (a.w + EPS);
    ((float4*)g_recip[m][b])[i] = r;
}

// ---------------------------------------------------------------------------
// Fused kernel: cp.async-pipelined PSD accumulate -> reduce -> parallel solve
// -> beamform from smem. One block per (b,f).
// ---------------------------------------------------------------------------
__device__ __forceinline__ int pidx(int c, int d) {
    return c * 7 - (c * (c - 1)) / 2 + (d - c - 1);
}

__device__ __forceinline__ void getS(const float* a, float invs,
                                     int r, int c, float& re, float& im) {
    const float IM0 = PSD_EPS + EPS;
    if (r == c)      { re = a[r] * invs;                 im = IM0; }
    else if (r < c)  { int p = pidx(r, c);
                       re = a[8 + 2 * p] * invs;         im = a[9 + 2 * p] * invs + IM0; }
    else             { int p = pidx(c, r);
                       re = a[8 + 2 * p] * invs;         im = -a[9 + 2 * p] * invs + IM0; }
}

__device__ __forceinline__ void accum_point(float* acc, const float* xr,
                                            const float* xi, float ms, float mn) {
    acc[64]  += ms;
    acc[129] += mn;
    #pragma unroll
    for (int c = 0; c < 8; c++) {
        float p = fmaf(xr[c], xr[c], xi[c] * xi[c]);
        acc[c]      = fmaf(ms, p, acc[c]);
        acc[65 + c] = fmaf(mn, p, acc[65 + c]);
    }
    #pragma unroll
    for (int c = 0; c < 8; c++) {
        #pragma unroll
        for (int d = c + 1; d < 8; d++) {
            int p = pidx(c, d);
            float orr = fmaf(xr[c], xr[d], xi[c] * xi[d]);
            float oii = fmaf(xi[c], xr[d], -xr[c] * xi[d]);
            acc[8 + 2 * p]  = fmaf(ms, orr, acc[8 + 2 * p]);
            acc[9 + 2 * p]  = fmaf(ms, oii, acc[9 + 2 * p]);
            acc[73 + 2 * p] = fmaf(mn, orr, acc[73 + 2 * p]);
            acc[74 + 2 * p] = fmaf(mn, oii, acc[74 + 2 * p]);
        }
    }
}

// dynamic smem: 16 rows of T floats (cm tile) + 2*T floats (ms,mn interleaved)
constexpr int DYN_SMEM = 18 * T * (int)sizeof(float);   // 108000 B

__global__ __launch_bounds__(128) void mvdr_fused_kernel(
    const float* __restrict__ sm, const float* __restrict__ nm,
    const float* __restrict__ cr, const float* __restrict__ ci,
    float* __restrict__ out) {
    extern __shared__ float tile[];     // rows 0..7: re ch c, rows 8..15: im ch c
    float* msn = tile + 16 * T;         // interleaved (ms, mn) per t

    int bf = blockIdx.x;
    int b = bf / F, f = bf % F;
    int tid = threadIdx.x;
    int lane = tid & 31, wid = tid >> 5;

    const float* crb = cr + (long long)b * C * FT + (long long)f * T;
    const float* cib = ci + (long long)b * C * FT + (long long)f * T;
    const float4* sm4 = (const float4*)(sm + (long long)b * FT + (long long)f * T);
    const float4* nm4 = (const float4*)(nm + (long long)b * FT + (long long)f * T);
    const float4* rs4 = (const float4*)(g_recip[0][b]);
    const float4* rn4 = (const float4*)(g_recip[1][b]);

    // ---- Issue the whole cm tile as NCHUNK cp.async groups (fire & forget) ----
    #pragma unroll 1
    for (int k = 0; k < NCHUNK; k++) {
        for (int e = tid; e < EPC; e += 128) {
            int r = e / CH_T4;
            int j = e - r * CH_T4 + CH_T4 * k;        // float4 index within row
            const float* src = (r < 8 ? crb + (long long)r * FT
                                      : cib + (long long)(r - 8) * FT) + 4 * j;
            cp16(smem_u32(tile + r * T + 4 * j), src);
        }
        cp_commit();
    }

    // ---- Prologue (overlapped with in-flight cp.asyncs): mask products ----
    float2* msn2 = (float2*)msn;
    for (int i = tid; i < T4; i += 128) {
        float4 s = sm4[i], n = nm4[i];
        float4 a = rs4[i], c = rn4[i];
        msn2[4 * i + 0] = make_float2(s.x * a.x, n.x * c.x);
        msn2[4 * i + 1] = make_float2(s.y * a.y, n.y * c.y);
        msn2[4 * i + 2] = make_float2(s.z * a.z, n.z * c.z);
        msn2[4 * i + 3] = make_float2(s.w * a.w, n.w * c.w);
    }

    // ---- Phase A: per-chunk wait + accumulate from smem ----
    float acc[130];
    #pragma unroll
    for (int k = 0; k < 130; k++) acc[k] = 0.f;

    #pragma unroll 1
    for (int k = 0; k < NCHUNK; k++) {
        if      (k == 0) cp_wait<4>();
        else if (k == 1) cp_wait<3>();
        else if (k == 2) cp_wait<2>();
        else if (k == 3) cp_wait<1>();
        else             cp_wait<0>();
        __syncthreads();    // chunk k visible to all; also covers msn on k=0
        for (int i = CH_T2 * k + tid; i < CH_T2 * (k + 1); i += 128) {
            float2 m0 = msn2[2 * i], m1 = msn2[2 * i + 1];
            float xr0[8], xi0[8], xr1[8], xi1[8];
            #pragma unroll
            for (int c = 0; c < 8; c++) {
                float2 vr = ((const float2*)(tile + c * T))[i];
                float2 vi = ((const float2*)(tile + (8 + c) * T))[i];
                xr0[c] = vr.x; xr1[c] = vr.y;
                xi0[c] = vi.x; xi1[c] = vi.y;
            }
            accum_point(acc, xr0, xi0, m0.x, m0.y);
            accum_point(acc, xr1, xi1, m1.x, m1.y);
        }
    }

    // ---- Phase B: deterministic reduction (warp shfl + cross-warp smem) ----
    __shared__ float sh[4][132];
    __shared__ float sacc[130];
    #pragma unroll
    for (int k = 0; k < 130; k++) {
        float v = acc[k];
        v += __shfl_down_sync(0xffffffffu, v, 16);
        v += __shfl_down_sync(0xffffffffu, v, 8);
        v += __shfl_down_sync(0xffffffffu, v, 4);
        v += __shfl_down_sync(0xffffffffu, v, 2);
        v += __shfl_down_sync(0xffffffffu, v, 1);
        if (lane == 0) sh[wid][k] = v;
    }
    __syncthreads();
    for (int k = tid; k < 130; k += 128)
        sacc[k] = sh[0][k] + sh[1][k] + sh[2][k] + sh[3][k];
    __syncthreads();

    // ---- Phase C: entry-parallel solve (threads 0..63) ----
    __shared__ float rowr[8], rowi[8], colr[8], coli[8];
    __shared__ float sur[8], sui[8], strv[2];
    __shared__ float swr[8], swi[8];
    const float* aS = &sacc[0];
    const float* aN = &sacc[65];
    const float IM0 = PSD_EPS + EPS;
    int i8 = tid >> 3, j8 = tid & 7;
    float nr = 0.f, ni = 0.f;

    if (tid < 64) {
        float invd = 1.0f / fmaxf(aN[64], PSD_EPS);
        if (i8 == j8)      { nr = aN[i8] * invd + EPS;  ni = IM0; }
        else if (i8 < j8)  { int p = pidx(i8, j8);
                             nr = aN[8 + 2 * p] * invd; ni = aN[9 + 2 * p] * invd + IM0; }
        else               { int p = pidx(j8, i8);
                             nr = aN[8 + 2 * p] * invd; ni = -aN[9 + 2 * p] * invd + IM0; }
    }

    // Gauss-Jordan, no pivoting (matrix is strongly diagonally dominant)
    #pragma unroll
    for (int k = 0; k < 8; k++) {
        if (tid < 64) {
            if (i8 == k) { rowr[j8] = nr; rowi[j8] = ni; }
            if (j8 == k) { colr[i8] = nr; coli[i8] = ni; }
        }
        __syncthreads();
        if (tid < 64) {
            float pr = rowr[k], pi = rowi[k];
            float s = 1.0f / fmaf(pr, pr, pi * pi);
            float qr = pr * s, qi = -pi * s;
            if (i8 == k) {
                if (j8 == k) { nr = qr; ni = qi; }
                else { float ar = nr, ai = ni;
                       nr = ar * qr - ai * qi; ni = ar * qi + ai * qr; }
            } else {
                float fr = colr[i8], fi = coli[i8];
                float gr = fr * qr - fi * qi, gi = fr * qi + fi * qr;
                if (j8 == k) { nr = -gr; ni = -gi; }
                else {
                    float br = rowr[j8], bi = rowi[j8];
                    nr -= gr * br - gi * bi;
                    ni -= gr * bi + gi * br;
                }
            }
        }
        __syncthreads();
    }

    if (tid < 64) {
        ni += EPS;
        float invs = 1.0f / fmaxf(aS[64], PSD_EPS);
        float sr, si;
        getS(aS, invs, j8, i8, sr, si);
        float tre = nr * sr - ni * si, tim = nr * si + ni * sr;
        getS(aS, invs, j8, 0, sr, si);
        float ue = nr * sr - ni * si, uim = nr * si + ni * sr;
        #pragma unroll
        for (int o = 1; o < 8; o <<= 1) {
            ue  += __shfl_xor_sync(0xffffffffu, ue, o);
            uim += __shfl_xor_sync(0xffffffffu, uim, o);
        }
        if (j8 == 0) { sur[i8] = ue; sui[i8] = uim; }
        #pragma unroll
        for (int o = 16; o >= 1; o >>= 1) {
            tre += __shfl_down_sync(0xffffffffu, tre, o);
            tim += __shfl_down_sync(0xffffffffu, tim, o);
        }
        if (lane == 0) { sh[wid][0] = tre; sh[wid][1] = tim; }
    }
    __syncthreads();
    if (tid == 0) {
        strv[0] = EPS + sh[0][0] + sh[1][0];
        strv[1] = sh[0][1] + sh[1][1];
    }
    __syncthreads();
    if (tid < 8) {
        float trr = strv[0], tri = strv[1];
        float tm = 1.0f / fmaf(trr, trr, tri * tri);
        float ur = sur[tid], ui = sui[tid];
        float wr = (ur * trr + ui * tri) * tm;
        float wi = (ui * trr - ur * tri) * tm;
        swr[tid] = wr;
        swi[tid] = -wi;                           // conj(weight)
    }
    __syncthreads();

    // ---- Phase D: beamform from smem, float4 along t ----
    float wr[8], wi[8];
    #pragma unroll
    for (int c = 0; c < 8; c++) { wr[c] = swr[c]; wi[c] = swi[c]; }
    float4* outr = (float4*)(out + (long long)bf * T);
    float4* outi = (float4*)(out + BFT + (long long)bf * T);
    for (int i = tid; i < T4; i += 128) {
        float4 orv = make_float4(0.f, 0.f, 0.f, 0.f);
        float4 oiv = make_float4(0.f, 0.f, 0.f, 0.f);
        #pragma unroll
        for (int c = 0; c < 8; c++) {
            float4 xr = ((const float4*)(tile + c * T))[i];
            float4 xi = ((const float4*)(tile + (8 + c) * T))[i];
            orv.x = fmaf(wr[c], xr.x, fmaf(-wi[c], xi.x, orv.x));
            orv.y = fmaf(wr[c], xr.y, fmaf(-wi[c], xi.y, orv.y));
            orv.z = fmaf(wr[c], xr.z, fmaf(-wi[c], xi.z, orv.z));
            orv.w = fmaf(wr[c], xr.w, fmaf(-wi[c], xi.w, orv.w));
            oiv.x = fmaf(wr[c], xi.x, fmaf(wi[c], xr.x, oiv.x));
            oiv.y = fmaf(wr[c], xi.y, fmaf(wi[c], xr.y, oiv.y));
            oiv.z = fmaf(wr[c], xi.z, fmaf(wi[c], xr.z, oiv.z));
            oiv.w = fmaf(wr[c], xi.w, fmaf(wi[c], xr.w, oiv.w));
        }
        outr[i] = orv;
        outi[i] = oiv;
    }
}

// ---------------------------------------------------------------------------
extern "C" void kernel_launch(void* const* d_in, const int* in_sizes, int n_in,
                              void* d_out, int out_size) {
    const float* sm = (const float*)d_in[0];
    const float* nm = (const float*)d_in[1];
    const float* cr = (const float*)d_in[2];
    const float* ci = (const float*)d_in[3];
    float* out = (float*)d_out;

    cudaFuncSetAttribute(mvdr_fused_kernel,
                         cudaFuncAttributeMaxDynamicSharedMemorySize, DYN_SMEM);

    mask_max_part<<<2 * B * NCH, 384>>>(sm, nm);
    mask_recip_kernel<<<16, 384>>>();
    mvdr_fused_kernel<<<BF, 128, DYN_SMEM>>>(sm, nm, cr, ci, out);
}